// round 1
// baseline (speedup 1.0000x reference)
#include <cuda_runtime.h>

// Morton (Z-order) decode: x[B, C, L] with L = 65536 laid out in Morton order
// -> out[B, C, 256, 256] where i = odd bits of the Morton index, j = even bits.
//
// Structure exploited: 4 consecutive Morton indices (aligned) form a 2x2 output
// block; 1024 consecutive form a 32x32 output tile. One block handles one tile:
//   - thread t loads float4 at src[tile*1024 + t*4]  (perfectly coalesced)
//   - writes two float2s to output rows (di, di+1) at column dj
// Per-warp store footprint per STG.64: 4 rows x 64B = 8 full 32B sectors.
// Pure HBM-bound; no shared memory required.

__global__ void __launch_bounds__(256, 8)
morton_decode_kernel(const float4* __restrict__ src, float* __restrict__ dst)
{
    const unsigned tile  = blockIdx.x;        // global tile id
    const unsigned slice = tile >> 6;         // (b*C + c) index; 64 tiles per slice
    const unsigned t6    = tile & 63u;        // tile position within slice (Morton order)

    // Deinterleave the 6 tile bits: odd bits -> i_tile (3b), even bits -> j_tile (3b)
    const unsigned i_tile = ((t6 >> 1) & 1u) | ((t6 >> 2) & 2u) | ((t6 >> 3) & 4u);
    const unsigned j_tile = ( t6       & 1u) | ((t6 >> 1) & 2u) | ((t6 >> 2) & 4u);

    const unsigned t = threadIdx.x;           // 0..255

    // Source morton offset within tile is s = t*4 (bits 0,1 zero).
    // dj collects even bits of s (>=bit2), di collects odd bits (>=bit3):
    //   dj = 2*t0 + 4*t2 + 8*t4 + 16*t6_bit
    //   di = 2*t1 + 4*t3 + 8*t5 + 16*t7_bit
    const unsigned dj = ((t & 1u)  << 1) | ( t & 4u)        | ((t & 16u) >> 1) | ((t & 64u)  >> 2);
    const unsigned di = ( t & 2u)        | ((t & 8u) >> 1)  | ((t & 32u) >> 2) | ((t & 128u) >> 3);

    // Coalesced 16B load of 4 consecutive Morton elements (a 2x2 block), streaming.
    const float4 v = __ldcs(src + (size_t)tile * 256u + t);

    const unsigned i = i_tile * 32u + di;     // output row within 256x256 map
    const unsigned j = j_tile * 32u + dj;     // output col (even)

    float* base = dst + (size_t)slice * 65536u + (size_t)i * 256u + j;

    // s+0 -> (i, j), s+1 -> (i, j+1), s+2 -> (i+1, j), s+3 -> (i+1, j+1)
    __stcs(reinterpret_cast<float2*>(base),        make_float2(v.x, v.y));
    __stcs(reinterpret_cast<float2*>(base + 256),  make_float2(v.z, v.w));
}

extern "C" void kernel_launch(void* const* d_in, const int* in_sizes, int n_in,
                              void* d_out, int out_size)
{
    const float4* src = (const float4*)d_in[0];
    float*        dst = (float*)d_out;

    // Total elements / 1024 elements-per-tile
    const int n_tiles = in_sizes[0] >> 10;    // 33,554,432 / 1024 = 32768
    morton_decode_kernel<<<n_tiles, 256>>>(src, dst);
}